// round 2
// baseline (speedup 1.0000x reference)
#include <cuda_runtime.h>

#define Bz    4
#define Cc    64
#define Hh    64
#define Ww    64
#define HW    4096
#define CHW   (Cc*HW)
#define PATCH 9
#define PROW  72     // padded row length (4 | 64 | 4)
#define PROWS 72     // padded row count  (4 | 64 | 4)
#define CHUNK 16     // channels staged per sync
#define NTHR  320    // 10 warps

// scratch
__device__ float g_inv1[Bz][HW];
__device__ float g_inv2[Bz][HW];
__device__ float g_f2n[Bz][Cc][PROWS][PROW];   // normalized f2, zero halos

// ---------------------------------------------------------------------------
// Kernel 1: per-pixel inverse L2 norms for both features
// ---------------------------------------------------------------------------
__global__ void invnorm_kernel(const float* __restrict__ f1,
                               const float* __restrict__ f2) {
    int idx  = blockIdx.x * blockDim.x + threadIdx.x;   // 0..32767
    int feat = idx >> 14;
    int pix  = idx & 16383;
    int b    = pix >> 12;
    int yx   = pix & 4095;
    const float* src = (feat ? f2 : f1) + b * CHW + yx;
    float s = 0.f;
#pragma unroll
    for (int c = 0; c < Cc; ++c) { float v = src[c * HW]; s += v * v; }
    float r = rsqrtf(s + 1e-6f);
    if (feat) g_inv2[b][yx] = r; else g_inv1[b][yx] = r;
}

// ---------------------------------------------------------------------------
// Kernel 2: write normalized f2 into zero-padded scratch
//   one thread per float4 of g_f2n: 4*64*72*18 = 331776 threads
// ---------------------------------------------------------------------------
__global__ void normpad_kernel(const float* __restrict__ f2) {
    int t   = blockIdx.x * 256 + threadIdx.x;
    int xq  = t % 18;
    int tmp = t / 18;
    int r   = tmp % 72;
    tmp    /= 72;
    int c   = tmp & 63;
    int b   = tmp >> 6;
    float4 val = make_float4(0.f, 0.f, 0.f, 0.f);
    int y = r - 4;
    if (y >= 0 && y < Hh && xq >= 1 && xq <= 16) {
        int x = (xq - 1) * 4;
        float4 v  = *(const float4*)(f2 + (b * Cc + c) * HW + y * Ww + x);
        float4 iv = *(const float4*)(&g_inv2[b][y * Ww + x]);
        val = make_float4(v.x * iv.x, v.y * iv.y, v.z * iv.z, v.w * iv.w);
    }
    *(float4*)&g_f2n[b][c][r][xq * 4] = val;
}

// ---------------------------------------------------------------------------
// Kernel 3: correlation + relu.
//   grid = B*H = 256 CTAs, 320 threads (10 warps).
//   warp w: dy pair p = w%5 (dy = 2p + lane/16), channel half = w/5.
//   lane: (half, xg) -> 4 pixels x0 = 4*(lane&15) of row y.
//   Channels staged 16 at a time into smem; channel halves reduced via smem.
// ---------------------------------------------------------------------------
__global__ __launch_bounds__(NTHR, 2)
void corr_kernel(const float* __restrict__ f1, float* __restrict__ out) {
    __shared__ float s_f2[CHUNK * PATCH * PROW];   // 16*9*72 = 10368 f = 41472 B
    __shared__ float s_f1[CHUNK * Ww];             // 1024 f  = 4096 B

    const int b    = blockIdx.x >> 6;
    const int y    = blockIdx.x & 63;
    const int tid  = threadIdx.x;
    const int w    = tid >> 5;
    const int lane = tid & 31;
    const int p    = (w >= 5) ? (w - 5) : w;       // dy pair index 0..4
    const int hi   = (w >= 5);                     // channel half
    const int dy   = 2 * p + (lane >> 4);          // 0..9 (9 = dead lanes)
    const int dyc  = (dy < PATCH) ? dy : 8;        // clamped for smem reads
    const int x0   = (lane & 15) << 2;

    float acc[PATCH][4];
#pragma unroll
    for (int i = 0; i < PATCH; ++i) { acc[i][0]=0.f; acc[i][1]=0.f; acc[i][2]=0.f; acc[i][3]=0.f; }

    const float* f2base = &g_f2n[b][0][y][0];           // + c*PROWS*PROW per ch
    const float* f1base = f1 + b * CHW + y * Ww;        // + c*HW per ch
    const float* s2w    = s_f2 + (hi ? 8 * PATCH * PROW : 0) + dyc * PROW + x0;
    const float* s1w    = s_f1 + (hi ? 8 * Ww : 0) + x0;

    for (int c0 = 0; c0 < Cc; c0 += CHUNK) {
        __syncthreads();
        // stage f2: 16 ch x 9 rows x 18 quads = 2592 float4
        for (int i = tid; i < CHUNK * PATCH * 18; i += NTHR) {
            int c   = i / (PATCH * 18);
            int rem = i - c * (PATCH * 18);
            int rr  = rem / 18;
            int q   = rem - rr * 18;
            float4 v = *(const float4*)(f2base + (c0 + c) * (PROWS * PROW) + rr * PROW + q * 4);
            *(float4*)&s_f2[(c * PATCH + rr) * PROW + q * 4] = v;
        }
        // stage f1: 16 ch x 16 quads = 256 float4
        if (tid < CHUNK * 16) {
            int c = tid >> 4;
            int q = tid & 15;
            *(float4*)&s_f1[c * Ww + q * 4] = *(const float4*)(f1base + (c0 + c) * HW + q * 4);
        }
        __syncthreads();

#pragma unroll
        for (int c = 0; c < 8; ++c) {
            float4 a = *(const float4*)(s1w + c * Ww);
            const float* s = s2w + c * (PATCH * PROW);
            float v[12];
            *(float4*)&v[0] = *(const float4*)(s);
            *(float4*)&v[4] = *(const float4*)(s + 4);
            *(float4*)&v[8] = *(const float4*)(s + 8);
#pragma unroll
            for (int dx = 0; dx < PATCH; ++dx) {
                acc[dx][0] += a.x * v[dx + 0];
                acc[dx][1] += a.y * v[dx + 1];
                acc[dx][2] += a.z * v[dx + 2];
                acc[dx][3] += a.w * v[dx + 3];
            }
        }
    }

    // ---- reduce channel halves (hi warps -> smem -> lo warps), then epilogue
    __syncthreads();
    float* s_part = s_f2;                 // reuse staging smem (needs 160*37*4 B)
    const int slot = (p * 32 + lane) * 37;
    if (hi) {
#pragma unroll
        for (int dx = 0; dx < PATCH; ++dx) {
            s_part[slot + dx*4 + 0] = acc[dx][0];
            s_part[slot + dx*4 + 1] = acc[dx][1];
            s_part[slot + dx*4 + 2] = acc[dx][2];
            s_part[slot + dx*4 + 3] = acc[dx][3];
        }
    }
    __syncthreads();
    if (!hi && dy < PATCH) {
        float4 iv = *(const float4*)(&g_inv1[b][y * Ww + x0]);
        float* op = out + (size_t)(b * 81 + dy * PATCH) * HW + y * Ww + x0;
#pragma unroll
        for (int dx = 0; dx < PATCH; ++dx) {
            float4 o;
            o.x = fmaxf((acc[dx][0] + s_part[slot + dx*4 + 0]) * iv.x, 0.f);
            o.y = fmaxf((acc[dx][1] + s_part[slot + dx*4 + 1]) * iv.y, 0.f);
            o.z = fmaxf((acc[dx][2] + s_part[slot + dx*4 + 2]) * iv.z, 0.f);
            o.w = fmaxf((acc[dx][3] + s_part[slot + dx*4 + 3]) * iv.w, 0.f);
            *(float4*)(op + dx * HW) = o;
        }
    }
}

// ---------------------------------------------------------------------------
extern "C" void kernel_launch(void* const* d_in, const int* in_sizes, int n_in,
                              void* d_out, int out_size) {
    const float* f1 = (const float*)d_in[0];
    const float* f2 = (const float*)d_in[1];
    float* out = (float*)d_out;

    invnorm_kernel<<<128, 256>>>(f1, f2);
    normpad_kernel<<<1296, 256>>>(f2);
    corr_kernel<<<Bz * Hh, NTHR>>>(f1, out);
}

// round 3
// speedup vs baseline: 1.2166x; 1.2166x over previous
#include <cuda_runtime.h>
#include <cstdint>

#define Bz    4
#define Cc    64
#define Hh    64
#define Ww    64
#define HW    4096
#define CHW   (Cc*HW)
#define PATCH 9
#define CHUNK 16
#define NCH   (Cc/CHUNK)          // 4
#define SROW  72
#define SROWS 10
#define BUF_FLOATS (CHUNK*SROWS*SROW)   // 11520
#define SMEM_BYTES (2*BUF_FLOATS*4)     // 92160
#define NTHR  288

// scratch
__device__ float g_inv1[Bz][HW];
__device__ float g_inv2p[Bz][72][72];   // padded inverse norms of f2 (halo = 1.0)

__device__ __forceinline__ uint32_t smem_u32(const void* p) {
    uint32_t a;
    asm("{ .reg .u64 t; cvta.to.shared.u64 t, %1; cvt.u32.u64 %0, t; }" : "=r"(a) : "l"(p));
    return a;
}
__device__ __forceinline__ void cp_async16(uint32_t dst, const float* src, int sz) {
    asm volatile("cp.async.cg.shared.global [%0], [%1], 16, %2;"
                 :: "r"(dst), "l"(src), "r"(sz) : "memory");
}
__device__ __forceinline__ void cp_commit() {
    asm volatile("cp.async.commit_group;" ::: "memory");
}
template<int N>
__device__ __forceinline__ void cp_wait() {
    asm volatile("cp.async.wait_group %0;" :: "n"(N) : "memory");
}

// ---------------------------------------------------------------------------
// Kernel 1: inverse L2 norms. 1 thread = (feat, b, pixel-quad, channel-group).
// 32768 threads; 16 float4 loads each (MLP=16); shfl-reduce over 4 cgroups.
// Also writes halo (=1.0) of padded inv2 map.
// ---------------------------------------------------------------------------
__global__ void invnorm_kernel(const float* __restrict__ f1,
                               const float* __restrict__ f2) {
    int idx  = blockIdx.x * 256 + threadIdx.x;          // 0..32767
    int cg   = idx & 3;
    int quad = (idx >> 2) & 1023;
    int b    = (idx >> 12) & 3;
    int feat = idx >> 14;
    const float* src = (feat ? f2 : f1) + b * CHW + quad * 4 + cg * 16 * HW;

    float4 s = make_float4(0.f, 0.f, 0.f, 0.f);
#pragma unroll
    for (int i = 0; i < 16; ++i) {
        float4 v = __ldg((const float4*)(src + i * HW));
        s.x += v.x * v.x; s.y += v.y * v.y; s.z += v.z * v.z; s.w += v.w * v.w;
    }
#pragma unroll
    for (int m = 1; m <= 2; m <<= 1) {
        s.x += __shfl_xor_sync(0xffffffffu, s.x, m);
        s.y += __shfl_xor_sync(0xffffffffu, s.y, m);
        s.z += __shfl_xor_sync(0xffffffffu, s.z, m);
        s.w += __shfl_xor_sync(0xffffffffu, s.w, m);
    }
    if (cg == 0) {
        float4 r;
        r.x = rsqrtf(s.x + 1e-6f); r.y = rsqrtf(s.y + 1e-6f);
        r.z = rsqrtf(s.z + 1e-6f); r.w = rsqrtf(s.w + 1e-6f);
        int y = quad >> 4, x = (quad & 15) << 2;
        if (feat == 0) {
            *(float4*)&g_inv1[b][quad * 4] = r;
        } else {
            *(float4*)&g_inv2p[b][y + 4][x + 4] = r;
        }
    }
    // halo of padded inv2 map (disjoint cells; value never matters since raw sum=0)
    if (idx < Bz * 72 * 72) {
        int bb = idx / 5184;
        int rc = idx - bb * 5184;
        int r  = rc / 72, cc = rc - r * 72;
        if (r < 4 || r >= 68 || cc < 4 || cc >= 68)
            g_inv2p[bb][r][cc] = 1.0f;
    }
}

// ---------------------------------------------------------------------------
// Kernel 2: correlation + relu. grid = B*(H/2) = 128 CTAs, 9 warps.
// warp = dy; lane = (ty in 0..1, x-quad in 0..15). Raw f2 staged in 16-channel
// chunks via cp.async (zero-filled halos), double buffered. inv1*inv2 applied
// in the epilogue.
// ---------------------------------------------------------------------------
__global__ __launch_bounds__(NTHR, 1)
void corr_kernel(const float* __restrict__ f1,
                 const float* __restrict__ f2,
                 float* __restrict__ out) {
    extern __shared__ float s_f2[];            // [2][CHUNK][SROWS][SROW]
    const uint32_t s_base = smem_u32(s_f2);

    const int b   = blockIdx.x >> 5;
    const int y0  = (blockIdx.x & 31) * 2;
    const int tid = threadIdx.x;
    const int dy  = tid >> 5;                  // warp = dy (0..8)
    const int lane = tid & 31;
    const int ty  = lane >> 4;
    const int x0  = (lane & 15) << 2;
    const int y   = y0 + ty;

    const float* f2b = f2 + b * CHW;
    const float* f1b = f1 + b * CHW + y * Ww + x0;

    // stage one 16-channel chunk into buffer `sel`
    auto stage = [&](int c0, int sel) {
        uint32_t dbase = s_base + sel * (BUF_FLOATS * 4);
#pragma unroll
        for (int it = 0; it < 10; ++it) {
            int i   = it * NTHR + tid;         // 0..2879
            int c   = i / 180;
            int rem = i - c * 180;
            int r   = rem / 18;
            int q   = rem - r * 18;
            int row = y0 + r - 4;
            bool valid = (row >= 0) & (row < Hh) & (q >= 1) & (q <= 16);
            const float* src = f2b + (valid ? ((c0 + c) * HW + row * Ww + (q - 1) * 4) : 0);
            uint32_t dst = dbase + (uint32_t)(((c * SROWS + r) * SROW + q * 4) * 4);
            cp_async16(dst, src, valid ? 16 : 0);
        }
        cp_commit();
    };

    float acc[PATCH][4];
#pragma unroll
    for (int i = 0; i < PATCH; ++i) { acc[i][0]=0.f; acc[i][1]=0.f; acc[i][2]=0.f; acc[i][3]=0.f; }

    stage(0, 0);

#pragma unroll 1
    for (int k = 0; k < NCH; ++k) {
        if (k + 1 < NCH) { stage((k + 1) * CHUNK, (k + 1) & 1); cp_wait<1>(); }
        else            { cp_wait<0>(); }
        __syncthreads();

        const float* sbuf = s_f2 + (k & 1) * BUF_FLOATS + (dy + ty) * SROW + x0;
        const float* f1c  = f1b + k * CHUNK * HW;
#pragma unroll 4
        for (int c = 0; c < CHUNK; ++c) {
            float4 a = __ldg((const float4*)(f1c + c * HW));
            const float* s = sbuf + c * (SROWS * SROW);
            float v[12];
            *(float4*)&v[0] = *(const float4*)(s);
            *(float4*)&v[4] = *(const float4*)(s + 4);
            *(float4*)&v[8] = *(const float4*)(s + 8);
#pragma unroll
            for (int dx = 0; dx < PATCH; ++dx) {
                acc[dx][0] += a.x * v[dx + 0];
                acc[dx][1] += a.y * v[dx + 1];
                acc[dx][2] += a.z * v[dx + 2];
                acc[dx][3] += a.w * v[dx + 3];
            }
        }
        __syncthreads();
    }

    // epilogue: scale by inv1 (this pixel) * inv2 (displaced pixel), relu, store
    float4 iv1 = *(const float4*)(&g_inv1[b][y * Ww + x0]);
    float e[12];
    *(float4*)&e[0] = *(const float4*)(&g_inv2p[b][y + dy][x0]);
    *(float4*)&e[4] = *(const float4*)(&g_inv2p[b][y + dy][x0 + 4]);
    *(float4*)&e[8] = *(const float4*)(&g_inv2p[b][y + dy][x0 + 8]);

    float* op = out + (size_t)(b * 81 + dy * PATCH) * HW + y * Ww + x0;
#pragma unroll
    for (int dx = 0; dx < PATCH; ++dx) {
        float4 o;
        o.x = fmaxf(acc[dx][0] * iv1.x * e[dx + 0], 0.f);
        o.y = fmaxf(acc[dx][1] * iv1.y * e[dx + 1], 0.f);
        o.z = fmaxf(acc[dx][2] * iv1.z * e[dx + 2], 0.f);
        o.w = fmaxf(acc[dx][3] * iv1.w * e[dx + 3], 0.f);
        *(float4*)(op + dx * HW) = o;
    }
}

// ---------------------------------------------------------------------------
extern "C" void kernel_launch(void* const* d_in, const int* in_sizes, int n_in,
                              void* d_out, int out_size) {
    const float* f1 = (const float*)d_in[0];
    const float* f2 = (const float*)d_in[1];
    float* out = (float*)d_out;

    cudaFuncSetAttribute(corr_kernel,
                         cudaFuncAttributeMaxDynamicSharedMemorySize, SMEM_BYTES);

    invnorm_kernel<<<128, 256>>>(f1, f2);
    corr_kernel<<<Bz * (Hh / 2), NTHR, SMEM_BYTES>>>(f1, f2, out);
}

// round 4
// speedup vs baseline: 1.2186x; 1.0017x over previous
#include <cuda_runtime.h>
#include <cstdint>

#define Bz    4
#define Cc    64
#define Hh    64
#define Ww    64
#define HW    4096
#define CHW   (Cc*HW)
#define PATCH 9
#define CHUNK 16
#define NCH   (Cc/CHUNK)          // 4
#define SROW  72
#define SROWS 10
#define F2BUF (CHUNK*SROWS*SROW)        // 11520 floats
#define F1BUF (CHUNK*2*Ww)              // 2048 floats
#define SMEM_FLOATS (2*(F2BUF+F1BUF))   // 27136
#define SMEM_BYTES  (SMEM_FLOATS*4)     // 108544
#define NTHR  288

// scratch
__device__ float g_inv1[Bz][HW];
__device__ float g_inv2p[Bz][72][72];   // padded inverse norms of f2 (halo = 1.0)

__device__ __forceinline__ uint32_t smem_u32(const void* p) {
    uint32_t a;
    asm("{ .reg .u64 t; cvta.to.shared.u64 t, %1; cvt.u32.u64 %0, t; }" : "=r"(a) : "l"(p));
    return a;
}
__device__ __forceinline__ void cp_async16(uint32_t dst, const float* src, int sz) {
    asm volatile("cp.async.cg.shared.global [%0], [%1], 16, %2;"
                 :: "r"(dst), "l"(src), "r"(sz) : "memory");
}
__device__ __forceinline__ void cp_commit() {
    asm volatile("cp.async.commit_group;" ::: "memory");
}
template<int N>
__device__ __forceinline__ void cp_wait() {
    asm volatile("cp.async.wait_group %0;" :: "n"(N) : "memory");
}

// ---------------------------------------------------------------------------
// Kernel 1: inverse L2 norms (proven in R3). 32768 threads, MLP=16, shfl-reduce.
// ---------------------------------------------------------------------------
__global__ void invnorm_kernel(const float* __restrict__ f1,
                               const float* __restrict__ f2) {
    int idx  = blockIdx.x * 256 + threadIdx.x;          // 0..32767
    int cg   = idx & 3;
    int quad = (idx >> 2) & 1023;
    int b    = (idx >> 12) & 3;
    int feat = idx >> 14;
    const float* src = (feat ? f2 : f1) + b * CHW + quad * 4 + cg * 16 * HW;

    float4 s = make_float4(0.f, 0.f, 0.f, 0.f);
#pragma unroll
    for (int i = 0; i < 16; ++i) {
        float4 v = __ldg((const float4*)(src + i * HW));
        s.x += v.x * v.x; s.y += v.y * v.y; s.z += v.z * v.z; s.w += v.w * v.w;
    }
#pragma unroll
    for (int m = 1; m <= 2; m <<= 1) {
        s.x += __shfl_xor_sync(0xffffffffu, s.x, m);
        s.y += __shfl_xor_sync(0xffffffffu, s.y, m);
        s.z += __shfl_xor_sync(0xffffffffu, s.z, m);
        s.w += __shfl_xor_sync(0xffffffffu, s.w, m);
    }
    if (cg == 0) {
        float4 r;
        r.x = rsqrtf(s.x + 1e-6f); r.y = rsqrtf(s.y + 1e-6f);
        r.z = rsqrtf(s.z + 1e-6f); r.w = rsqrtf(s.w + 1e-6f);
        int y = quad >> 4, x = (quad & 15) << 2;
        if (feat == 0) {
            *(float4*)&g_inv1[b][quad * 4] = r;
        } else {
            *(float4*)&g_inv2p[b][y + 4][x + 4] = r;
        }
    }
    if (idx < Bz * 72 * 72) {
        int bb = idx / 5184;
        int rc = idx - bb * 5184;
        int r  = rc / 72, cc = rc - r * 72;
        if (r < 4 || r >= 68 || cc < 4 || cc >= 68)
            g_inv2p[bb][r][cc] = 1.0f;
    }
}

// ---------------------------------------------------------------------------
// Kernel 2: correlation + relu. grid = B*(H/2) = 128 CTAs, 9 warps.
// warp = dy; lane = (ty, x-quad). BOTH f1 and f2 staged via double-buffered
// cp.async; compute loop is smem-only (no global latency in the hot path).
// ---------------------------------------------------------------------------
__global__ __launch_bounds__(NTHR, 1)
void corr_kernel(const float* __restrict__ f1,
                 const float* __restrict__ f2,
                 float* __restrict__ out) {
    extern __shared__ float smem[];
    // layout: [2][F2BUF] f2 buffers, then [2][F1BUF] f1 buffers
    float* s_f2 = smem;
    float* s_f1 = smem + 2 * F2BUF;
    const uint32_t s2_base = smem_u32(s_f2);
    const uint32_t s1_base = smem_u32(s_f1);

    const int b    = blockIdx.x >> 5;
    const int y0   = (blockIdx.x & 31) * 2;
    const int tid  = threadIdx.x;
    const int dy   = tid >> 5;                 // warp = dy (0..8)
    const int lane = tid & 31;
    const int ty   = lane >> 4;
    const int x0   = (lane & 15) << 2;
    const int y    = y0 + ty;

    const float* f2b = f2 + b * CHW;
    const float* f1b = f1 + b * CHW + y0 * Ww;

    auto stage = [&](int c0, int sel) {
        // f2: 16 ch x 10 rows x 18 quads = 2880 cp.async (zero-filled halos)
        uint32_t d2 = s2_base + sel * (F2BUF * 4);
#pragma unroll
        for (int it = 0; it < 10; ++it) {
            int i   = it * NTHR + tid;
            int c   = i / 180;
            int rem = i - c * 180;
            int r   = rem / 18;
            int q   = rem - r * 18;
            int row = y0 + r - 4;
            bool valid = (row >= 0) & (row < Hh) & (q >= 1) & (q <= 16);
            const float* src = f2b + (valid ? ((c0 + c) * HW + row * Ww + (q - 1) * 4) : 0);
            cp_async16(d2 + (uint32_t)(((c * SROWS + r) * SROW + q * 4) * 4), src, valid ? 16 : 0);
        }
        // f1: 16 ch x 2 rows x 16 quads = 512 cp.async
        uint32_t d1 = s1_base + sel * (F1BUF * 4);
#pragma unroll
        for (int it = 0; it < 2; ++it) {
            int i = it * NTHR + tid;
            if (i < CHUNK * 32) {
                int c  = i >> 5;
                int rq = i & 31;               // row*16 + quad
                cp_async16(d1 + (uint32_t)((c * 128 + rq * 4) * 4),
                           f1b + (c0 + c) * HW + rq * 4, 16);
            }
        }
        cp_commit();
    };

    float acc[PATCH][4];
#pragma unroll
    for (int i = 0; i < PATCH; ++i) { acc[i][0]=0.f; acc[i][1]=0.f; acc[i][2]=0.f; acc[i][3]=0.f; }

    stage(0, 0);

#pragma unroll 1
    for (int k = 0; k < NCH; ++k) {
        if (k + 1 < NCH) { stage((k + 1) * CHUNK, (k + 1) & 1); cp_wait<1>(); }
        else            { cp_wait<0>(); }
        __syncthreads();

        const float* sbuf = s_f2 + (k & 1) * F2BUF + (dy + ty) * SROW + x0;
        const float* abuf = s_f1 + (k & 1) * F1BUF + ty * Ww + x0;
#pragma unroll 8
        for (int c = 0; c < CHUNK; ++c) {
            float4 a = *(const float4*)(abuf + c * 128);
            const float* s = sbuf + c * (SROWS * SROW);
            float v[12];
            *(float4*)&v[0] = *(const float4*)(s);
            *(float4*)&v[4] = *(const float4*)(s + 4);
            *(float4*)&v[8] = *(const float4*)(s + 8);
#pragma unroll
            for (int dx = 0; dx < PATCH; ++dx) {
                acc[dx][0] += a.x * v[dx + 0];
                acc[dx][1] += a.y * v[dx + 1];
                acc[dx][2] += a.z * v[dx + 2];
                acc[dx][3] += a.w * v[dx + 3];
            }
        }
        __syncthreads();
    }

    // epilogue: scale by inv1 (this pixel) * inv2 (displaced pixel), relu, store
    float4 iv1 = *(const float4*)(&g_inv1[b][y * Ww + x0]);
    float e[12];
    *(float4*)&e[0] = *(const float4*)(&g_inv2p[b][y + dy][x0]);
    *(float4*)&e[4] = *(const float4*)(&g_inv2p[b][y + dy][x0 + 4]);
    *(float4*)&e[8] = *(const float4*)(&g_inv2p[b][y + dy][x0 + 8]);

    float* op = out + (size_t)(b * 81 + dy * PATCH) * HW + y * Ww + x0;
#pragma unroll
    for (int dx = 0; dx < PATCH; ++dx) {
        float4 o;
        o.x = fmaxf(acc[dx][0] * iv1.x * e[dx + 0], 0.f);
        o.y = fmaxf(acc[dx][1] * iv1.y * e[dx + 1], 0.f);
        o.z = fmaxf(acc[dx][2] * iv1.z * e[dx + 2], 0.f);
        o.w = fmaxf(acc[dx][3] * iv1.w * e[dx + 3], 0.f);
        *(float4*)(op + dx * HW) = o;
    }
}

// ---------------------------------------------------------------------------
extern "C" void kernel_launch(void* const* d_in, const int* in_sizes, int n_in,
                              void* d_out, int out_size) {
    const float* f1 = (const float*)d_in[0];
    const float* f2 = (const float*)d_in[1];
    float* out = (float*)d_out;

    cudaFuncSetAttribute(corr_kernel,
                         cudaFuncAttributeMaxDynamicSharedMemorySize, SMEM_BYTES);

    invnorm_kernel<<<128, 256>>>(f1, f2);
    corr_kernel<<<Bz * (Hh / 2), NTHR, SMEM_BYTES>>>(f1, f2, out);
}